// round 16
// baseline (speedup 1.0000x reference)
#include <cuda_runtime.h>
#include <math.h>
#include <stdint.h>

#define NV     12
#define BATCH  4096
#define DIM    128
#define ALPHA  0.4f
#define BETA   2.0f
#define LAMDA  2.0f

#define B_PER_BLK 4            // batch elements per block (1 warp each)
#define THREADS   128
#define NBLOCKS   (BATCH / B_PER_BLK)    // 1024

// Per-block partials + ticket (device globals, zero-initialized)
__device__ float g_pl[NBLOCKS];
__device__ float g_pc[NBLOCKS];
__device__ float g_pm[NBLOCKS];
__device__ float g_pa[NBLOCKS];
__device__ float g_pmin[NBLOCKS];
__device__ unsigned int g_ticket;

__device__ __forceinline__ float dot4(float4 a, float4 b) {
    return a.x * b.x + a.y * b.y + a.z * b.z + a.w * b.w;
}
__device__ __forceinline__ float sqdiff4(float4 a, float4 b) {
    float x = a.x - b.x, y = a.y - b.y, z = a.z - b.z, w = a.w - b.w;
    return x * x + y * y + z * z + w * w;
}

// order-preserving float -> u32 key (total order, works for negatives)
__device__ __forceinline__ unsigned fkey(float x) {
    unsigned b = __float_as_uint(x);
    return b ^ ((b & 0x80000000u) ? 0xFFFFFFFFu : 0x80000000u);
}
__device__ __forceinline__ float fkey_inv(unsigned k) {
    unsigned b = (k & 0x80000000u) ? (k ^ 0x80000000u) : ~k;
    return __uint_as_float(b);
}

__global__ __launch_bounds__(THREADS, 7)
void pil_fused(const float* __restrict__ SV_A, const float* __restrict__ SV_N,
               const float* __restrict__ MV_A, const float* __restrict__ MV_N,
               float* __restrict__ out, int out_size)
{
    __shared__ float r_loss[B_PER_BLK], r_cnt[B_PER_BLK];
    __shared__ float r_mc[B_PER_BLK], r_ac[B_PER_BLK], r_mn[B_PER_BLK];
    __shared__ float red[5][THREADS];
    __shared__ int   s_islast;

    const int tid  = threadIdx.x;
    const int lane = tid & 31;
    const int w    = tid >> 5;       // warp = local batch element 0..3
    const int h    = lane >> 4;      // dim-half: dims [h*64, h*64+64)
    const int t    = lane & 15;
    const int ti   = t >> 2;         // A rows 3*ti..3*ti+2
    const int tj   = t & 3;          // N rows 3*tj..3*tj+2
    const int bg   = blockIdx.x * B_PER_BLK + w;

    // ---- register-direct Gram + in-register norms (no smem, no barriers)
    const float4* A0 = reinterpret_cast<const float4*>(
        SV_A + ((size_t)(3 * ti) * BATCH + bg) * DIM + h * 64);
    const float4* A1 = reinterpret_cast<const float4*>(
        SV_A + ((size_t)(3 * ti + 1) * BATCH + bg) * DIM + h * 64);
    const float4* A2 = reinterpret_cast<const float4*>(
        SV_A + ((size_t)(3 * ti + 2) * BATCH + bg) * DIM + h * 64);
    const float4* N0 = reinterpret_cast<const float4*>(
        SV_N + ((size_t)(3 * tj) * BATCH + bg) * DIM + h * 64);
    const float4* N1 = reinterpret_cast<const float4*>(
        SV_N + ((size_t)(3 * tj + 1) * BATCH + bg) * DIM + h * 64);
    const float4* N2 = reinterpret_cast<const float4*>(
        SV_N + ((size_t)(3 * tj + 2) * BATCH + bg) * DIM + h * 64);

    float G[3][3] = {{0.f,0.f,0.f},{0.f,0.f,0.f},{0.f,0.f,0.f}};
    float nA[3] = {0.f, 0.f, 0.f};
    float nN[3] = {0.f, 0.f, 0.f};

    #pragma unroll
    for (int k4 = 0; k4 < 16; ++k4) {       // this lane's 64-dim half
        float4 a0 = A0[k4];
        float4 a1 = A1[k4];
        float4 a2 = A2[k4];
        float4 n0 = N0[k4];
        float4 n1 = N1[k4];
        float4 n2 = N2[k4];
        G[0][0] += dot4(a0, n0); G[0][1] += dot4(a0, n1); G[0][2] += dot4(a0, n2);
        G[1][0] += dot4(a1, n0); G[1][1] += dot4(a1, n1); G[1][2] += dot4(a1, n2);
        G[2][0] += dot4(a2, n0); G[2][1] += dot4(a2, n1); G[2][2] += dot4(a2, n2);
        nA[0] += dot4(a0, a0);
        nA[1] += dot4(a1, a1);
        nA[2] += dot4(a2, a2);
        nN[0] += dot4(n0, n0);
        nN[1] += dot4(n1, n1);
        nN[2] += dot4(n2, n2);
    }

    // ---- hoist argmin-independent epilogue loads (overlap the tail)
    float4 ma  = reinterpret_cast<const float4*>(MV_A + (size_t)bg * DIM)[lane];
    float4 mn_ = reinterpret_cast<const float4*>(MV_N + (size_t)bg * DIM)[lane];

    // ---- combine 64-dim halves (single offset-16 butterfly stage)
    #pragma unroll
    for (int r = 0; r < 3; ++r) {
        nA[r] += __shfl_xor_sync(0xffffffffu, nA[r], 16);
        nN[r] += __shfl_xor_sync(0xffffffffu, nN[r], 16);
        #pragma unroll
        for (int cc = 0; cc < 3; ++cc)
            G[r][cc] += __shfl_xor_sync(0xffffffffu, G[r][cc], 16);
    }

    // ---- d = nA + nN - 2G, local argmin with flat-index tie-break
    float dmin = 3.4e38f;
    int   imin = 0;
    #pragma unroll
    for (int r = 0; r < 3; ++r) {
        #pragma unroll
        for (int cc = 0; cc < 3; ++cc) {
            float d  = nA[r] + nN[cc] - 2.f * G[r][cc];
            int   fl = (3 * ti + r) * NV + (3 * tj + cc);
            if (d < dmin || (d == dmin && fl < imin)) { dmin = d; imin = fl; }
        }
    }
    // ---- warp argmin via 2 REDUX ops
    unsigned mykey = fkey(dmin);
    unsigned gkey  = __reduce_min_sync(0xffffffffu, mykey);
    unsigned cand  = (mykey == gkey) ? (unsigned)imin : 0xFFFFFFFFu;
    imin = (int)__reduce_min_sync(0xffffffffu, cand);
    dmin = fkey_inv(gkey);

    // ---- dependent conf-row loads: 1 float4 per lane per array
    const int confA = imin / NV;
    const int confN = imin - confA * NV;

    float4 fa = reinterpret_cast<const float4*>(SV_A + ((size_t)confA * BATCH + bg) * DIM)[lane];
    float4 fn = reinterpret_cast<const float4*>(SV_N + ((size_t)confN * BATCH + bg) * DIM)[lane];

    float smv = sqdiff4(ma, mn_);
    float sa  = sqdiff4(ma, fa);
    float sc  = sqdiff4(mn_, fn);
    #pragma unroll
    for (int o = 1; o < 32; o <<= 1) {
        smv += __shfl_xor_sync(0xffffffffu, smv, o);
        sa  += __shfl_xor_sync(0xffffffffu, sa,  o);
        sc  += __shfl_xor_sync(0xffffffffu, sc,  o);
    }

    if (lane == 0) {
        float mc       = fmaxf(dmin, 0.f);
        float mv_inter = sqrtf(smv);
        float a_cl     = sqrtf(sa);
        float c_in     = sqrtf(sc);
        float loss = LAMDA * (fmaxf(BETA - mc, 0.f) + fmaxf(BETA - mv_inter, 0.f))
                   + fmaxf(a_cl - ALPHA, 0.f) + fmaxf(c_in - ALPHA, 0.f);
        float sqmc = sqrtf(mc);
        r_loss[w] = loss;
        r_cnt[w]  = (loss != 0.f) ? 1.f : 0.f;
        r_mc[w]   = sqmc;
        r_ac[w]   = sqrtf(a_cl) + sqrtf(c_in);
        r_mn[w]   = sqmc;
    }
    __syncthreads();

    // ---- per-block partial (fixed order -> deterministic) + ticket
    if (tid == 0) {
        float sl = 0.f, sn = 0.f, sm = 0.f, sa2 = 0.f, mn = 3.4e38f;
        #pragma unroll
        for (int i = 0; i < B_PER_BLK; ++i) {
            sl  += r_loss[i];
            sn  += r_cnt[i];
            sm  += r_mc[i];
            sa2 += r_ac[i];
            mn   = fminf(mn, r_mn[i]);
        }
        g_pl[blockIdx.x]   = sl;
        g_pc[blockIdx.x]   = sn;
        g_pm[blockIdx.x]   = sm;
        g_pa[blockIdx.x]   = sa2;
        g_pmin[blockIdx.x] = mn;
        __threadfence();
        unsigned int prev = atomicAdd(&g_ticket, 1u);
        s_islast = (prev == NBLOCKS - 1) ? 1 : 0;
    }
    __syncthreads();

    // ---- last block: deterministic final reduction over 1024 partials
    if (s_islast) {
        __threadfence();
        float al = 0.f, ac = 0.f, am = 0.f, aa = 0.f, amn = 3.4e38f;
        #pragma unroll
        for (int q = 0; q < NBLOCKS / THREADS; ++q) {   // 8, fixed order
            int i = tid + q * THREADS;
            al += g_pl[i];
            ac += g_pc[i];
            am += g_pm[i];
            aa += g_pa[i];
            amn = fminf(amn, g_pmin[i]);
        }
        red[0][tid] = al; red[1][tid] = ac; red[2][tid] = am;
        red[3][tid] = aa; red[4][tid] = amn;
        __syncthreads();
        for (int o = THREADS / 2; o > 0; o >>= 1) {
            if (tid < o) {
                red[0][tid] += red[0][tid + o];
                red[1][tid] += red[1][tid + o];
                red[2][tid] += red[2][tid + o];
                red[3][tid] += red[3][tid + o];
                red[4][tid]  = fminf(red[4][tid], red[4][tid + o]);
            }
            __syncthreads();
        }
        if (tid == 0) {
            const float inv = 1.f / (float)BATCH;
            if (out_size > 0) out[0] = red[0][0] * inv;          // avg_loss
            if (out_size > 1) out[1] = red[1][0];                // count_nonzero
            if (out_size > 2) out[2] = red[2][0] * inv;          // mean(sqrt(mc))
            if (out_size > 3) out[3] = 0.5f * red[3][0] * inv;   // cluster means
            if (out_size > 4) out[4] = red[4][0];                // min(sqrt(mc))
            for (int i = 5; i < out_size; ++i) out[i] = 0.f;
            g_ticket = 0;      // reset for next graph replay
        }
    }
}

extern "C" void kernel_launch(void* const* d_in, const int* in_sizes, int n_in,
                              void* d_out, int out_size)
{
    const float* SV_A = (const float*)d_in[0];
    const float* SV_N = (const float*)d_in[1];
    const float* MV_A = (const float*)d_in[2];
    const float* MV_N = (const float*)d_in[3];
    (void)in_sizes; (void)n_in;

    pil_fused<<<NBLOCKS, THREADS>>>(SV_A, SV_N, MV_A, MV_N,
                                    (float*)d_out, out_size);
}

// round 17
// speedup vs baseline: 1.5409x; 1.5409x over previous
#include <cuda_runtime.h>
#include <math.h>
#include <stdint.h>

#define NV     12
#define BATCH  4096
#define DIM    128
#define ALPHA  0.4f
#define BETA   2.0f
#define LAMDA  2.0f

#define B_PER_BLK 4            // batch elements per block (1 warp each)
#define THREADS   128
#define NBLOCKS   (BATCH / B_PER_BLK)    // 1024
#define CHUNK     32           // k-dims staged per chunk
#define NCHUNK    4
#define PITCH     36           // floats per smem row (32 data + 4 pad) = 144B
#define ROWS      24           // 12 A rows + 12 N rows
#define CBUF      (ROWS * PITCH)         // 864 floats per chunk buffer
#define NSTAGE    6            // float4 staged per lane per chunk

// Per-block partials + ticket (device globals, zero-initialized)
__device__ float g_pl[NBLOCKS];
__device__ float g_pc[NBLOCKS];
__device__ float g_pm[NBLOCKS];
__device__ float g_pa[NBLOCKS];
__device__ float g_pmin[NBLOCKS];
__device__ unsigned int g_ticket;

__device__ __forceinline__ float sqdiff4(float4 a, float4 b) {
    float x = a.x - b.x, y = a.y - b.y, z = a.z - b.z, w = a.w - b.w;
    return x * x + y * y + z * z + w * w;
}
__device__ __forceinline__ void cp_async16(uint32_t saddr, const void* gptr) {
    asm volatile("cp.async.cg.shared.global [%0], [%1], 16;"
                 :: "r"(saddr), "l"(gptr));
}
#define CP_COMMIT()  asm volatile("cp.async.commit_group;")
#define CP_WAIT(N)   asm volatile("cp.async.wait_group %0;" :: "n"(N))

// packed f32x2 FMA: acc(2xf32) += a(2xf32) * b(2xf32)   [Blackwell FFMA2]
__device__ __forceinline__ void fma2(uint64_t& acc, uint64_t a, uint64_t b) {
    asm("fma.rn.f32x2 %0, %1, %2, %0;" : "+l"(acc) : "l"(a), "l"(b));
}
__device__ __forceinline__ float unpack_sum(uint64_t p) {
    float lo = __uint_as_float((unsigned)(p & 0xFFFFFFFFull));
    float hi = __uint_as_float((unsigned)(p >> 32));
    return lo + hi;
}

// order-preserving float -> u32 key
__device__ __forceinline__ unsigned fkey(float x) {
    unsigned b = __float_as_uint(x);
    return b ^ ((b & 0x80000000u) ? 0xFFFFFFFFu : 0x80000000u);
}
__device__ __forceinline__ float fkey_inv(unsigned k) {
    unsigned b = (k & 0x80000000u) ? (k ^ 0x80000000u) : ~k;
    return __uint_as_float(b);
}

__global__ __launch_bounds__(THREADS, 7)
void pil_fused(const float* __restrict__ SV_A, const float* __restrict__ SV_N,
               const float* __restrict__ MV_A, const float* __restrict__ MV_N,
               float* __restrict__ out, int out_size)
{
    // 4 warps x 2 chunk buffers x 864 floats = 27.6 KB.
    __shared__ float tile[4 * 2 * CBUF];
    __shared__ float nrm[B_PER_BLK * ROWS];
    __shared__ float r_loss[B_PER_BLK], r_cnt[B_PER_BLK];
    __shared__ float r_mc[B_PER_BLK], r_ac[B_PER_BLK], r_mn[B_PER_BLK];
    __shared__ float red[5][THREADS];
    __shared__ int   s_islast;

    const int tid  = threadIdx.x;
    const int lane = tid & 31;
    const int w    = tid >> 5;       // warp = local batch element 0..3
    const int h    = lane >> 4;      // 16-dim half within a 32-chunk
    const int t    = lane & 15;
    const int ti   = t >> 2;         // A rows 3*ti..3*ti+2
    const int tj   = t & 3;          // N rows 3*tj..3*tj+2
    const int bg   = blockIdx.x * B_PER_BLK + w;

    float* wbuf = &tile[w * 2 * CBUF];
    const uint32_t wbase = (uint32_t)__cvta_generic_to_shared(wbuf);

    // ---- staging addresses: 6 float4 per lane per chunk (warp-local)
    const float* gsrc[NSTAGE];
    uint32_t     soff[NSTAGE];
    #pragma unroll
    for (int s = 0; s < NSTAGE; ++s) {
        int f   = lane + 32 * s;               // 0..191
        int row = f >> 3;                      // 0..23
        int k4  = f & 7;
        const float* base = (row < NV)
            ? SV_A + ((size_t)row        * BATCH + bg) * DIM
            : SV_N + ((size_t)(row - NV) * BATCH + bg) * DIM;
        gsrc[s] = base + k4 * 4;
        soff[s] = (uint32_t)((row * PITCH + k4 * 4) * 4);
    }

    // prologue: issue chunks 0 and 1
    #pragma unroll
    for (int s = 0; s < NSTAGE; ++s)
        cp_async16(wbase + soff[s], gsrc[s]);
    CP_COMMIT();
    #pragma unroll
    for (int s = 0; s < NSTAGE; ++s)
        cp_async16(wbase + (uint32_t)(CBUF * 4) + soff[s], gsrc[s] + CHUNK);
    CP_COMMIT();

    // packed f32x2 accumulators
    uint64_t Gp[3][3] = {{0ull,0ull,0ull},{0ull,0ull,0ull},{0ull,0ull,0ull}};
    uint64_t np0 = 0ull, np1 = 0ull;

    #pragma unroll
    for (int c = 0; c < NCHUNK; ++c) {
        if (c < NCHUNK - 1) { CP_WAIT(1); } else { CP_WAIT(0); }
        __syncwarp();
        const float* tb = wbuf + (c & 1) * CBUF;

        // ---- norm partial: lanes 0..23 each own one row (32 dims), packed
        if (lane < ROWS) {
            const float* rb = tb + lane * PITCH;
            #pragma unroll
            for (int k4 = 0; k4 < 8; k4 += 2) {
                ulonglong2 v0 = *reinterpret_cast<const ulonglong2*>(rb + k4 * 4);
                ulonglong2 v1 = *reinterpret_cast<const ulonglong2*>(rb + (k4 + 1) * 4);
                fma2(np0, v0.x, v0.x); fma2(np1, v0.y, v0.y);
                fma2(np0, v1.x, v1.x); fma2(np1, v1.y, v1.y);
            }
        }

        // ---- 3x3 register-tiled Gram, packed f32x2 (2 FMA2 per dot4)
        const float* A0 = tb + (3 * ti)      * PITCH + h * 16;
        const float* N0 = tb + (NV + 3 * tj) * PITCH + h * 16;
        #pragma unroll
        for (int k4 = 0; k4 < 4; ++k4) {
            ulonglong2 a0 = *reinterpret_cast<const ulonglong2*>(A0 + 0 * PITCH + k4 * 4);
            ulonglong2 a1 = *reinterpret_cast<const ulonglong2*>(A0 + 1 * PITCH + k4 * 4);
            ulonglong2 a2 = *reinterpret_cast<const ulonglong2*>(A0 + 2 * PITCH + k4 * 4);
            ulonglong2 n0 = *reinterpret_cast<const ulonglong2*>(N0 + 0 * PITCH + k4 * 4);
            ulonglong2 n1 = *reinterpret_cast<const ulonglong2*>(N0 + 1 * PITCH + k4 * 4);
            ulonglong2 n2 = *reinterpret_cast<const ulonglong2*>(N0 + 2 * PITCH + k4 * 4);
            fma2(Gp[0][0], a0.x, n0.x); fma2(Gp[0][0], a0.y, n0.y);
            fma2(Gp[0][1], a0.x, n1.x); fma2(Gp[0][1], a0.y, n1.y);
            fma2(Gp[0][2], a0.x, n2.x); fma2(Gp[0][2], a0.y, n2.y);
            fma2(Gp[1][0], a1.x, n0.x); fma2(Gp[1][0], a1.y, n0.y);
            fma2(Gp[1][1], a1.x, n1.x); fma2(Gp[1][1], a1.y, n1.y);
            fma2(Gp[1][2], a1.x, n2.x); fma2(Gp[1][2], a1.y, n2.y);
            fma2(Gp[2][0], a2.x, n0.x); fma2(Gp[2][0], a2.y, n0.y);
            fma2(Gp[2][1], a2.x, n1.x); fma2(Gp[2][1], a2.y, n1.y);
            fma2(Gp[2][2], a2.x, n2.x); fma2(Gp[2][2], a2.y, n2.y);
        }

        // refill consumed buffer with chunk c+2
        if (c + 2 < NCHUNK) {
            __syncwarp();
            uint32_t dst = wbase + (uint32_t)((c & 1) * CBUF * 4);
            #pragma unroll
            for (int s = 0; s < NSTAGE; ++s)
                cp_async16(dst + soff[s], gsrc[s] + (c + 2) * CHUNK);
            CP_COMMIT();
        }
    }

    // ---- hoist argmin-independent epilogue loads (overlap the tail)
    float4 ma  = reinterpret_cast<const float4*>(MV_A + (size_t)bg * DIM)[lane];
    float4 mn_ = reinterpret_cast<const float4*>(MV_N + (size_t)bg * DIM)[lane];

    // unpack packed accumulators
    float G[3][3];
    #pragma unroll
    for (int r = 0; r < 3; ++r)
        #pragma unroll
        for (int cc = 0; cc < 3; ++cc)
            G[r][cc] = unpack_sum(Gp[r][cc]);

    // publish full-dim norms (warp-local region)
    if (lane < ROWS) nrm[w * ROWS + lane] = unpack_sum(np0) + unpack_sum(np1);

    // ---- combine 16-dim halves of G (offset-16 butterfly)
    #pragma unroll
    for (int r = 0; r < 3; ++r)
        #pragma unroll
        for (int cc = 0; cc < 3; ++cc)
            G[r][cc] += __shfl_xor_sync(0xffffffffu, G[r][cc], 16);
    __syncwarp();                  // nrm visible within warp

    // ---- d = na + nn - 2G, local argmin with flat-index tie-break
    float dmin = 3.4e38f;
    int   imin = 0;
    #pragma unroll
    for (int r = 0; r < 3; ++r) {
        float na = nrm[w * ROWS + 3 * ti + r];
        #pragma unroll
        for (int cc = 0; cc < 3; ++cc) {
            float nn = nrm[w * ROWS + NV + 3 * tj + cc];
            float d  = na + nn - 2.f * G[r][cc];
            int   fl = (3 * ti + r) * NV + (3 * tj + cc);
            if (d < dmin || (d == dmin && fl < imin)) { dmin = d; imin = fl; }
        }
    }
    // ---- warp argmin via 2 REDUX ops
    unsigned mykey = fkey(dmin);
    unsigned gkey  = __reduce_min_sync(0xffffffffu, mykey);
    unsigned cand  = (mykey == gkey) ? (unsigned)imin : 0xFFFFFFFFu;
    imin = (int)__reduce_min_sync(0xffffffffu, cand);
    dmin = fkey_inv(gkey);

    // ---- dependent conf-row loads: 1 float4 per lane per array
    const int confA = imin / NV;
    const int confN = imin - confA * NV;

    float4 fa = reinterpret_cast<const float4*>(SV_A + ((size_t)confA * BATCH + bg) * DIM)[lane];
    float4 fn = reinterpret_cast<const float4*>(SV_N + ((size_t)confN * BATCH + bg) * DIM)[lane];

    float smv = sqdiff4(ma, mn_);
    float sa  = sqdiff4(ma, fa);
    float sc  = sqdiff4(mn_, fn);
    #pragma unroll
    for (int o = 1; o < 32; o <<= 1) {
        smv += __shfl_xor_sync(0xffffffffu, smv, o);
        sa  += __shfl_xor_sync(0xffffffffu, sa,  o);
        sc  += __shfl_xor_sync(0xffffffffu, sc,  o);
    }

    if (lane == 0) {
        float mc       = fmaxf(dmin, 0.f);
        float mv_inter = sqrtf(smv);
        float a_cl     = sqrtf(sa);
        float c_in     = sqrtf(sc);
        float loss = LAMDA * (fmaxf(BETA - mc, 0.f) + fmaxf(BETA - mv_inter, 0.f))
                   + fmaxf(a_cl - ALPHA, 0.f) + fmaxf(c_in - ALPHA, 0.f);
        float sqmc = sqrtf(mc);
        r_loss[w] = loss;
        r_cnt[w]  = (loss != 0.f) ? 1.f : 0.f;
        r_mc[w]   = sqmc;
        r_ac[w]   = sqrtf(a_cl) + sqrtf(c_in);
        r_mn[w]   = sqmc;
    }
    __syncthreads();

    // ---- per-block partial (fixed order -> deterministic) + ticket
    if (tid == 0) {
        float sl = 0.f, sn = 0.f, sm = 0.f, sa2 = 0.f, mn = 3.4e38f;
        #pragma unroll
        for (int i = 0; i < B_PER_BLK; ++i) {
            sl  += r_loss[i];
            sn  += r_cnt[i];
            sm  += r_mc[i];
            sa2 += r_ac[i];
            mn   = fminf(mn, r_mn[i]);
        }
        g_pl[blockIdx.x]   = sl;
        g_pc[blockIdx.x]   = sn;
        g_pm[blockIdx.x]   = sm;
        g_pa[blockIdx.x]   = sa2;
        g_pmin[blockIdx.x] = mn;
        __threadfence();
        unsigned int prev = atomicAdd(&g_ticket, 1u);
        s_islast = (prev == NBLOCKS - 1) ? 1 : 0;
    }
    __syncthreads();

    // ---- last block: deterministic final reduction over 1024 partials
    if (s_islast) {
        __threadfence();
        float al = 0.f, ac = 0.f, am = 0.f, aa = 0.f, amn = 3.4e38f;
        #pragma unroll
        for (int q = 0; q < NBLOCKS / THREADS; ++q) {   // 8, fixed order
            int i = tid + q * THREADS;
            al += g_pl[i];
            ac += g_pc[i];
            am += g_pm[i];
            aa += g_pa[i];
            amn = fminf(amn, g_pmin[i]);
        }
        red[0][tid] = al; red[1][tid] = ac; red[2][tid] = am;
        red[3][tid] = aa; red[4][tid] = amn;
        __syncthreads();
        for (int o = THREADS / 2; o > 0; o >>= 1) {
            if (tid < o) {
                red[0][tid] += red[0][tid + o];
                red[1][tid] += red[1][tid + o];
                red[2][tid] += red[2][tid + o];
                red[3][tid] += red[3][tid + o];
                red[4][tid]  = fminf(red[4][tid], red[4][tid + o]);
            }
            __syncthreads();
        }
        if (tid == 0) {
            const float inv = 1.f / (float)BATCH;
            if (out_size > 0) out[0] = red[0][0] * inv;          // avg_loss
            if (out_size > 1) out[1] = red[1][0];                // count_nonzero
            if (out_size > 2) out[2] = red[2][0] * inv;          // mean(sqrt(mc))
            if (out_size > 3) out[3] = 0.5f * red[3][0] * inv;   // cluster means
            if (out_size > 4) out[4] = red[4][0];                // min(sqrt(mc))
            for (int i = 5; i < out_size; ++i) out[i] = 0.f;
            g_ticket = 0;      // reset for next graph replay
        }
    }
}

extern "C" void kernel_launch(void* const* d_in, const int* in_sizes, int n_in,
                              void* d_out, int out_size)
{
    const float* SV_A = (const float*)d_in[0];
    const float* SV_N = (const float*)d_in[1];
    const float* MV_A = (const float*)d_in[2];
    const float* MV_N = (const float*)d_in[3];
    (void)in_sizes; (void)n_in;

    pil_fused<<<NBLOCKS, THREADS>>>(SV_A, SV_N, MV_A, MV_N,
                                    (float*)d_out, out_size);
}